// round 9
// baseline (speedup 1.0000x reference)
#include <cuda_runtime.h>

#define NPTS 4096
#define NB   8
#define KNN  20
#define CO   64
#define CTA  256
#define Q    8
#define ITER (NPTS / CTA)   // 16 point-iterations per thread
#define PREI 2              // prefilter: first 512 points
#define TCAP 64

__device__ float4 g_xp[NB * NPTS];   // {x, y, z, -0.5*|p|^2}
__device__ float4 g_wf[CO * 2];      // {w0,w1,w2,w3}, {w4,w5,inv,shift}

__global__ void prep_kernel(const float* __restrict__ x,
                            const float* __restrict__ W,
                            const float* __restrict__ gamma_,
                            const float* __restrict__ beta_,
                            const float* __restrict__ mean_,
                            const float* __restrict__ var_)
{
    int idx = blockIdx.x * blockDim.x + threadIdx.x;
    if (idx < NB * NPTS) {
        int b = idx >> 12, p = idx & (NPTS - 1);
        const float* xb = x + (size_t)b * 3 * NPTS;
        float px = xb[p], py = xb[NPTS + p], pz = xb[2 * NPTS + p];
        g_xp[idx] = make_float4(px, py, pz, -0.5f * (px*px + py*py + pz*pz));
    }
    if (blockIdx.x == 0 && threadIdx.x < CO) {
        int o = threadIdx.x;
        float inv   = gamma_[o] * rsqrtf(var_[o] + 1e-5f);
        float shift = beta_[o] - mean_[o] * inv;
        g_wf[2*o]   = make_float4(W[6*o+0], W[6*o+1], W[6*o+2], W[6*o+3]);
        g_wf[2*o+1] = make_float4(W[6*o+4], W[6*o+5], inv, shift);
    }
}

// key = mono(dot(q,p) - |p|^2/2); dropping the per-query constant -|q|^2/2
// preserves per-query ordering exactly.
__device__ __forceinline__ unsigned keyof(float qx, float qy, float qz, float4 v)
{
    float s = fmaf(qx, v.x, fmaf(qy, v.y, fmaf(qz, v.z, v.w)));
    unsigned bb = __float_as_uint(s);
    return bb ^ (unsigned)(((int)bb >> 31) | 0x80000000);
}

// Warp-level descending suffix scan over 256 bins; exactly one lane gets sel>=0.
__device__ __forceinline__ void warp_scan_select(const int* h, int needv,
                                                 int& selBin, int& selBefore, int& selCnt)
{
    int lane = threadIdx.x & 31;
    int base = 255 - (lane << 3);
    int c[8]; int tsum = 0;
    #pragma unroll
    for (int j = 0; j < 8; j++) { c[j] = h[base - j]; tsum += c[j]; }
    int cum = tsum;
    #pragma unroll
    for (int off = 1; off < 32; off <<= 1) {
        int t = __shfl_up_sync(0xffffffffu, cum, off);
        if (lane >= off) cum += t;
    }
    int cumBefore = cum - tsum;
    selBin = -1;
    if (cumBefore < needv && needv <= cum) {
        int acc = cumBefore;
        #pragma unroll
        for (int j = 0; j < 8; j++) {
            if (acc + c[j] >= needv) { selBin = base - j; selBefore = acc; selCnt = c[j]; break; }
            acc += c[j];
        }
    }
}

__global__ __launch_bounds__(CTA)
void edgeconv_kernel(float* __restrict__ out)
{
    __shared__ int      hist[Q][256];       // 8 KB
    __shared__ int      pb_s[Q];
    __shared__ unsigned pf_s[Q];
    __shared__ int      sh_s[Q], need_s[Q], cnt_s[Q];
    __shared__ int      cntW[Q], cntT[Q];
    __shared__ int      knn_s[Q][KNN];
    __shared__ unsigned tkey[Q][TCAP];
    __shared__ int      tidx[Q][TCAP];
    __shared__ float4   nbr[Q][KNN];
    __shared__ float    sqx[Q], sqy[Q], sqz[Q];

    const int b    = blockIdx.y;
    const int n0   = blockIdx.x * Q;
    const int tid  = threadIdx.x;
    const int lane = tid & 31;
    const int wid  = tid >> 5;
    unsigned lt_mask; asm("mov.u32 %0, %%lanemask_lt;" : "=r"(lt_mask));

    const float4* __restrict__ xp = g_xp + (size_t)b * NPTS;

    #pragma unroll
    for (int i = 0; i < (Q * 256) / CTA; i++) ((int*)hist)[i * CTA + tid] = 0;
    if (tid < Q) { cntW[tid] = 0; cntT[tid] = 0; }
    if (tid < Q) { float4 t = xp[n0 + tid]; sqx[tid] = t.x; sqy[tid] = t.y; sqz[tid] = t.z; }

    float qx[Q], qy[Q], qz[Q];
    #pragma unroll
    for (int j = 0; j < Q; j++) {
        float4 t = xp[n0 + j];
        qx[j] = t.x; qy[j] = t.y; qz[j] = t.z;
    }
    __syncthreads();

    // ---- pass A: first 512 points, full insert
    #pragma unroll
    for (int i = 0; i < PREI; i++) {
        float4 v = xp[i * CTA + tid];
        #pragma unroll
        for (int j = 0; j < Q; j++) {
            unsigned u = keyof(qx[j], qy[j], qz[j], v);
            int bin = (int)(u >> 24);
            unsigned mk = __match_any_sync(0xffffffffu, bin);
            if (!(mk & lt_mask)) atomicAdd(&hist[j][bin], __popc(mk));
        }
    }
    __syncthreads();

    // ---- mini-scan: warp j finds provisional bin pb[j] (>=20 keys at/above it)
    {
        int sb, sbefore, scnt;
        warp_scan_select(hist[wid], KNN, sb, sbefore, scnt);
        if (sb >= 0) pb_s[wid] = sb;
    }
    __syncthreads();

    int pbr[Q];
    #pragma unroll
    for (int j = 0; j < Q; j++) pbr[j] = pb_s[j];

    // ---- pass B: remaining points, insert only bins >= pb (exact pruning)
    for (int i = PREI; i < ITER; i++) {
        float4 v = xp[i * CTA + tid];
        #pragma unroll
        for (int j = 0; j < Q; j++) {
            unsigned u = keyof(qx[j], qy[j], qz[j], v);
            int bin = (int)(u >> 24);
            bool ok = bin >= pbr[j];
            int mb = ok ? bin : -1;
            unsigned mk = __match_any_sync(0xffffffffu, mb);
            if (ok && !(mk & lt_mask)) atomicAdd(&hist[j][bin], __popc(mk));
        }
    }
    __syncthreads();

    // ---- final scan: warp j selects threshold bin for query j
    {
        int sb, sbefore, scnt;
        warp_scan_select(hist[wid], KNN, sb, sbefore, scnt);
        if (sb >= 0) {
            pf_s[wid]   = (unsigned)sb;
            need_s[wid] = KNN - sbefore;
            cnt_s[wid]  = scnt;
            sh_s[wid]   = 24;
        }
    }
    __syncthreads();

    // ---- refine (rare): narrow threshold bin by 8 bits while population > TCAP
    for (int rr = 0; rr < 3; rr++) {
        unsigned act = 0;
        #pragma unroll
        for (int j = 0; j < Q; j++)
            if (cnt_s[j] > TCAP && sh_s[j] > 0) act |= (1u << j);
        if (!act) break;
        unsigned pfr[Q]; int shr[Q];
        #pragma unroll
        for (int j = 0; j < Q; j++) { pfr[j] = pf_s[j]; shr[j] = sh_s[j]; }
        __syncthreads();                       // snapshots done before hist reuse
        #pragma unroll
        for (int i = 0; i < (Q * 256) / CTA; i++) {
            int idx = i * CTA + tid;
            if ((act >> (idx >> 8)) & 1) ((int*)hist)[idx] = 0;
        }
        __syncthreads();
        for (int i = 0; i < ITER; i++) {
            float4 v = xp[i * CTA + tid];
            #pragma unroll
            for (int j = 0; j < Q; j++) {
                if (!((act >> j) & 1)) continue;
                unsigned u = keyof(qx[j], qy[j], qz[j], v);
                bool ok = (u >> shr[j]) == pfr[j];
                int mb = ok ? (int)((u >> (shr[j] - 8)) & 255u) : -1;
                unsigned mk = __match_any_sync(0xffffffffu, mb);
                if (ok && !(mk & lt_mask)) atomicAdd(&hist[j][mb], __popc(mk));
            }
        }
        __syncthreads();
        if ((act >> wid) & 1) {
            int needv = need_s[wid];           // read before any write (same warp)
            unsigned pfo = pf_s[wid];
            int sho = sh_s[wid];
            int sb, sbefore, scnt;
            warp_scan_select(hist[wid], needv, sb, sbefore, scnt);
            if (sb >= 0) {
                pf_s[wid]   = (pfo << 8) | (unsigned)sb;
                sh_s[wid]   = sho - 8;
                need_s[wid] = needv - sbefore;
                cnt_s[wid]  = scnt;
            }
        }
        __syncthreads();
    }

    // ---- collect pass: recompute keys, split winners / boundary ties
    {
        unsigned pfr[Q]; int shr[Q];
        #pragma unroll
        for (int j = 0; j < Q; j++) { pfr[j] = pf_s[j]; shr[j] = sh_s[j]; }
        for (int i = 0; i < ITER; i++) {
            float4 v = xp[i * CTA + tid];
            int p = i * CTA + tid;
            #pragma unroll
            for (int j = 0; j < Q; j++) {
                unsigned u  = keyof(qx[j], qy[j], qz[j], v);
                unsigned hi = u >> shr[j];
                if (hi >= pfr[j]) {
                    if (hi > pfr[j]) {
                        knn_s[j][atomicAdd(&cntW[j], 1)] = p;
                    } else {
                        int pos = atomicAdd(&cntT[j], 1);
                        if (pos < TCAP) { tkey[j][pos] = u; tidx[j][pos] = p; }
                    }
                }
            }
        }
    }
    __syncthreads();

    // ---- tie rank: warp j resolves query j by (value desc, index asc)
    {
        int j = wid;
        int cnt   = cntT[j] < TCAP ? cntT[j] : TCAP;
        int needv = need_s[j];
        int baseW = cntW[j];
        for (int e = lane; e < cnt; e += 32) {
            unsigned mk = tkey[j][e]; int mi = tidx[j][e];
            int rank = 0;
            for (int t2 = 0; t2 < cnt; t2++) {
                unsigned kj = tkey[j][t2]; int ij = tidx[j][t2];
                rank += (kj > mk) || (kj == mk && ij < mi);
            }
            if (rank < needv) knn_s[j][baseW + rank] = mi;
        }
    }
    __syncthreads();

    // ---- gather neighbor coords
    if (tid < Q * KNN) {
        int j = tid / KNN, k = tid % KNN;
        nbr[j][k] = xp[knn_s[j][k]];
    }
    __syncthreads();

    // ---- edge MLP: 512 (j,o) outputs on 256 threads
    #pragma unroll
    for (int r = 0; r < 2; r++) {
        int idx = tid + r * CTA;
        int j = idx >> 6;          // uniform per warp
        int o = idx & 63;
        float qxx = sqx[j], qyy = sqy[j], qzz = sqz[j];   // LDS broadcast
        float4 wa = g_wf[2*o];
        float4 wb = g_wf[2*o + 1];
        float cpart = fmaf(qxx, wa.w, fmaf(qyy, wb.x, qzz * wb.y));
        float m = -3.4028235e38f;
        #pragma unroll
        for (int k = 0; k < KNN; k++) {
            float4 p = nbr[j][k];
            float y = fmaf(p.x - qxx, wa.x,
                      fmaf(p.y - qyy, wa.y,
                      fmaf(p.z - qzz, wa.z, cpart)));
            y = fmaf(y, wb.z, wb.w);
            y = (y >= 0.0f) ? y : 0.2f * y;
            m = fmaxf(m, y);
        }
        out[(size_t)b * CO * NPTS + (size_t)o * NPTS + n0 + j] = m;
    }
}

extern "C" void kernel_launch(void* const* d_in, const int* in_sizes, int n_in,
                              void* d_out, int out_size)
{
    const float* x      = (const float*)d_in[0];
    const float* W      = (const float*)d_in[1];
    const float* gamma_ = (const float*)d_in[2];
    const float* beta_  = (const float*)d_in[3];
    const float* mean_  = (const float*)d_in[4];
    const float* var_   = (const float*)d_in[5];
    float* out = (float*)d_out;

    prep_kernel<<<(NB * NPTS + 255) / 256, 256>>>(x, W, gamma_, beta_, mean_, var_);
    dim3 grid(NPTS / Q, NB);
    edgeconv_kernel<<<grid, CTA>>>(out);
}

// round 10
// speedup vs baseline: 1.3982x; 1.3982x over previous
#include <cuda_runtime.h>

#define NPTS 4096
#define NB   8
#define KNN  20
#define CO   64
#define CTA  256
#define Q    4
#define ITER (NPTS / CTA)   // 16
#define PREI 2              // calibration: first 512 points
#define CAP  640            // candidate buffer per query
#define TCAP 64

__device__ float4 g_xp[NB * NPTS];   // {x, y, z, -0.5*|p|^2}
__device__ float4 g_wf[CO * 2];      // {w0,w1,w2,w3}, {w4,w5,inv,shift}

__global__ void prep_kernel(const float* __restrict__ x,
                            const float* __restrict__ W,
                            const float* __restrict__ gamma_,
                            const float* __restrict__ beta_,
                            const float* __restrict__ mean_,
                            const float* __restrict__ var_)
{
    int idx = blockIdx.x * blockDim.x + threadIdx.x;
    if (idx < NB * NPTS) {
        int b = idx >> 12, p = idx & (NPTS - 1);
        const float* xb = x + (size_t)b * 3 * NPTS;
        float px = xb[p], py = xb[NPTS + p], pz = xb[2 * NPTS + p];
        g_xp[idx] = make_float4(px, py, pz, -0.5f * (px*px + py*py + pz*pz));
    }
    if (blockIdx.x == 0 && threadIdx.x < CO) {
        int o = threadIdx.x;
        float inv   = gamma_[o] * rsqrtf(var_[o] + 1e-5f);
        float shift = beta_[o] - mean_[o] * inv;
        g_wf[2*o]   = make_float4(W[6*o+0], W[6*o+1], W[6*o+2], W[6*o+3]);
        g_wf[2*o+1] = make_float4(W[6*o+4], W[6*o+5], inv, shift);
    }
}

// key = mono(dot(q,p) - |p|^2/2); per-query constant dropped (order-preserving).
__device__ __forceinline__ unsigned keyof(float qx, float qy, float qz, float4 v)
{
    float s = fmaf(qx, v.x, fmaf(qy, v.y, fmaf(qz, v.z, v.w)));
    unsigned bb = __float_as_uint(s);
    return bb ^ (unsigned)(((int)bb >> 31) | 0x80000000);
}

// Warp-level descending suffix scan over 256 bins; exactly one lane gets sel>=0.
__device__ __forceinline__ void warp_scan_select(const int* h, int needv,
                                                 int& selBin, int& selBefore, int& selCnt)
{
    int lane = threadIdx.x & 31;
    int base = 255 - (lane << 3);
    int c[8]; int tsum = 0;
    #pragma unroll
    for (int j = 0; j < 8; j++) { c[j] = h[base - j]; tsum += c[j]; }
    int cum = tsum;
    #pragma unroll
    for (int off = 1; off < 32; off <<= 1) {
        int t = __shfl_up_sync(0xffffffffu, cum, off);
        if (lane >= off) cum += t;
    }
    int cumBefore = cum - tsum;
    selBin = -1;
    if (cumBefore < needv && needv <= cum) {
        int acc = cumBefore;
        #pragma unroll
        for (int j = 0; j < 8; j++) {
            if (acc + c[j] >= needv) { selBin = base - j; selBefore = acc; selCnt = c[j]; break; }
            acc += c[j];
        }
    }
}

__global__ __launch_bounds__(CTA)
void edgeconv_kernel(float* __restrict__ out)
{
    __shared__ int      hist[Q][256];        // 4 KB
    __shared__ unsigned ckey[Q][CAP];        // 10 KB
    __shared__ int      cidx[Q][CAP];        // 10 KB
    __shared__ int      cntC[Q], cntW[Q], cntT[Q];
    __shared__ int      pb_s[Q];
    __shared__ unsigned pf_s[Q];
    __shared__ int      sh_s[Q], need_s[Q], cnt_s[Q];
    __shared__ int      knn_s[Q][KNN];
    __shared__ unsigned tkey[Q][TCAP];
    __shared__ int      tidx[Q][TCAP];
    __shared__ float4   nbr[Q][KNN];
    __shared__ float    sq[Q][3];

    const int b    = blockIdx.y;
    const int n0   = blockIdx.x * Q;
    const int tid  = threadIdx.x;
    const int lane = tid & 31;
    const int wid  = tid >> 5;
    unsigned lt_mask; asm("mov.u32 %0, %%lanemask_lt;" : "=r"(lt_mask));

    const float4* __restrict__ xp = g_xp + (size_t)b * NPTS;

    #pragma unroll
    for (int i = 0; i < (Q * 256) / CTA; i++) ((int*)hist)[i * CTA + tid] = 0;
    if (tid < Q) {
        cntC[tid] = 0; cntW[tid] = 0; cntT[tid] = 0;
        float4 t = xp[n0 + tid];
        sq[tid][0] = t.x; sq[tid][1] = t.y; sq[tid][2] = t.z;
    }

    float qx[Q], qy[Q], qz[Q];
    #pragma unroll
    for (int j = 0; j < Q; j++) {
        float4 t = xp[n0 + j];
        qx[j] = t.x; qy[j] = t.y; qz[j] = t.z;
    }
    __syncthreads();

    // ---- pass A: calibration — first 512 points, full hist insert (match-aggregated)
    #pragma unroll
    for (int i = 0; i < PREI; i++) {
        float4 v = xp[i * CTA + tid];
        #pragma unroll
        for (int j = 0; j < Q; j++) {
            unsigned u = keyof(qx[j], qy[j], qz[j], v);
            int bin = (int)(u >> 24);
            unsigned mk = __match_any_sync(0xffffffffu, bin);
            if (!(mk & lt_mask)) atomicAdd(&hist[j][bin], __popc(mk));
        }
    }
    __syncthreads();

    // ---- provisional threshold pb[j]: warps 0..3
    if (wid < Q) {
        int sb, sbefore, scnt;
        warp_scan_select(hist[wid], KNN, sb, sbefore, scnt);
        if (sb >= 0) pb_s[wid] = sb;
    }
    __syncthreads();

    int pbr[Q];
    #pragma unroll
    for (int j = 0; j < Q; j++) pbr[j] = pb_s[j];

    // ---- pass B: single full sweep; candidates appended; hist for i>=PREI only
    for (int i = 0; i < ITER; i++) {
        float4 v = xp[i * CTA + tid];
        int p = i * CTA + tid;
        #pragma unroll
        for (int j = 0; j < Q; j++) {
            unsigned u = keyof(qx[j], qy[j], qz[j], v);
            int bin = (int)(u >> 24);
            if (bin >= pbr[j]) {
                int pos = atomicAdd(&cntC[j], 1);
                if (pos < CAP) { ckey[j][pos] = u; cidx[j][pos] = p; }
                if (i >= PREI) atomicAdd(&hist[j][bin], 1);
            }
        }
    }
    __syncthreads();

    // ---- final threshold: warps 0..3
    if (wid < Q) {
        int sb, sbefore, scnt;
        warp_scan_select(hist[wid], KNN, sb, sbefore, scnt);
        if (sb >= 0) {
            pf_s[wid]   = (unsigned)sb;
            need_s[wid] = KNN - sbefore;
            cnt_s[wid]  = scnt;
            sh_s[wid]   = 24;
        }
    }
    __syncthreads();

    // ---- refine (rare): full-rescan, 8 bits per round, snapshot-disciplined
    for (int rr = 0; rr < 3; rr++) {
        unsigned act = 0;
        #pragma unroll
        for (int j = 0; j < Q; j++)
            if (cnt_s[j] > TCAP && sh_s[j] > 0) act |= (1u << j);
        if (!act) break;
        unsigned pfr[Q]; int shr[Q];
        #pragma unroll
        for (int j = 0; j < Q; j++) { pfr[j] = pf_s[j]; shr[j] = sh_s[j]; }
        __syncthreads();
        #pragma unroll
        for (int i = 0; i < (Q * 256) / CTA; i++) {
            int idx2 = i * CTA + tid;
            if ((act >> (idx2 >> 8)) & 1) ((int*)hist)[idx2] = 0;
        }
        __syncthreads();
        for (int i = 0; i < ITER; i++) {
            float4 v = xp[i * CTA + tid];
            #pragma unroll
            for (int j = 0; j < Q; j++) {
                if (!((act >> j) & 1)) continue;
                unsigned u = keyof(qx[j], qy[j], qz[j], v);
                if ((u >> shr[j]) == pfr[j])
                    atomicAdd(&hist[j][(u >> (shr[j] - 8)) & 255u], 1);
            }
        }
        __syncthreads();
        if (wid < Q && ((act >> wid) & 1)) {
            int needv = need_s[wid];
            unsigned pfo = pf_s[wid];
            int sho = sh_s[wid];
            int sb, sbefore, scnt;
            warp_scan_select(hist[wid], needv, sb, sbefore, scnt);
            if (sb >= 0) {
                pf_s[wid]   = (pfo << 8) | (unsigned)sb;
                sh_s[wid]   = sho - 8;
                need_s[wid] = needv - sbefore;
                cnt_s[wid]  = scnt;
            }
        }
        __syncthreads();
    }

    // ---- collection, fast path: warps j and j+4 sweep candidate buffer of query j
    {
        int j = wid & (Q - 1);
        int half = wid >> 2;                 // 0 or 1
        int cc = cntC[j];
        if (cc <= CAP) {
            unsigned pf = pf_s[j];
            int      sh = sh_s[j];
            for (int e = lane + 32 * half; e < cc; e += 64) {
                unsigned u  = ckey[j][e];
                unsigned hi = u >> sh;
                if (hi >= pf) {
                    if (hi > pf) {
                        knn_s[j][atomicAdd(&cntW[j], 1)] = cidx[j][e];
                    } else {
                        int pos = atomicAdd(&cntT[j], 1);
                        if (pos < TCAP) { tkey[j][pos] = u; tidx[j][pos] = cidx[j][e]; }
                    }
                }
            }
        }
    }
    __syncthreads();

    // ---- collection, fallback (buffer overflow): full rescan for flagged queries
    {
        unsigned ovf = 0;
        #pragma unroll
        for (int j = 0; j < Q; j++) if (cntC[j] > CAP) ovf |= (1u << j);
        if (ovf) {
            for (int j = 0; j < Q; j++) {
                if (!((ovf >> j) & 1)) continue;
                unsigned pf = pf_s[j];
                int      sh = sh_s[j];
                for (int i = 0; i < ITER; i++) {
                    float4 v = xp[i * CTA + tid];
                    unsigned u  = keyof(qx[j], qy[j], qz[j], v);
                    unsigned hi = u >> sh;
                    if (hi >= pf) {
                        if (hi > pf) {
                            knn_s[j][atomicAdd(&cntW[j], 1)] = i * CTA + tid;
                        } else {
                            int pos = atomicAdd(&cntT[j], 1);
                            if (pos < TCAP) { tkey[j][pos] = u; tidx[j][pos] = i * CTA + tid; }
                        }
                    }
                }
            }
            __syncthreads();
        }
    }

    // ---- tie rank: warp j resolves query j by (value desc, index asc)
    if (wid < Q) {
        int j = wid;
        int cnt   = cntT[j] < TCAP ? cntT[j] : TCAP;
        int needv = need_s[j];
        int baseW = cntW[j];
        for (int e = lane; e < cnt; e += 32) {
            unsigned mk = tkey[j][e]; int mi = tidx[j][e];
            int rank = 0;
            for (int t2 = 0; t2 < cnt; t2++) {
                unsigned kj = tkey[j][t2]; int ij = tidx[j][t2];
                rank += (kj > mk) || (kj == mk && ij < mi);
            }
            if (rank < needv) knn_s[j][baseW + rank] = mi;
        }
    }
    __syncthreads();

    // ---- gather neighbor coords
    if (tid < Q * KNN) {
        int j = tid / KNN, k = tid % KNN;
        nbr[j][k] = xp[knn_s[j][k]];
    }
    __syncthreads();

    // ---- edge MLP: Q*CO = 256 outputs, one per thread
    {
        int j = tid >> 6;                    // uniform per pair of warps
        int o = tid & 63;
        float qxx = sq[j][0], qyy = sq[j][1], qzz = sq[j][2];
        float4 wa = g_wf[2*o];
        float4 wb = g_wf[2*o + 1];
        float cpart = fmaf(qxx, wa.w, fmaf(qyy, wb.x, qzz * wb.y));
        float m = -3.4028235e38f;
        #pragma unroll
        for (int k = 0; k < KNN; k++) {
            float4 p = nbr[j][k];
            float y = fmaf(p.x - qxx, wa.x,
                      fmaf(p.y - qyy, wa.y,
                      fmaf(p.z - qzz, wa.z, cpart)));
            y = fmaf(y, wb.z, wb.w);
            y = (y >= 0.0f) ? y : 0.2f * y;
            m = fmaxf(m, y);
        }
        out[(size_t)b * CO * NPTS + (size_t)o * NPTS + n0 + j] = m;
    }
}

extern "C" void kernel_launch(void* const* d_in, const int* in_sizes, int n_in,
                              void* d_out, int out_size)
{
    const float* x      = (const float*)d_in[0];
    const float* W      = (const float*)d_in[1];
    const float* gamma_ = (const float*)d_in[2];
    const float* beta_  = (const float*)d_in[3];
    const float* mean_  = (const float*)d_in[4];
    const float* var_   = (const float*)d_in[5];
    float* out = (float*)d_out;

    prep_kernel<<<(NB * NPTS + 255) / 256, 256>>>(x, W, gamma_, beta_, mean_, var_);
    dim3 grid(NPTS / Q, NB);
    edgeconv_kernel<<<grid, CTA>>>(out);
}

// round 11
// speedup vs baseline: 1.6784x; 1.2003x over previous
#include <cuda_runtime.h>

#define NPTS 4096
#define NB   8
#define KNN  20
#define CO   64
#define CTA  256
#define SLOTS 16            // keys per thread (in smem)
#define PREI  2             // calibration iterations (512 points)
#define TIE_CAP 128

__device__ float4 g_xp[NB * NPTS];   // {x, y, z, -0.5*|p|^2}
__device__ float4 g_wf[CO * 2];      // per o: {w0,w1,w2,w3}, {w4,w5,inv,shift}

__global__ void prep_kernel(const float* __restrict__ x,
                            const float* __restrict__ W,
                            const float* __restrict__ gamma_,
                            const float* __restrict__ beta_,
                            const float* __restrict__ mean_,
                            const float* __restrict__ var_)
{
    int idx = blockIdx.x * blockDim.x + threadIdx.x;
    if (idx < NB * NPTS) {
        int b = idx >> 12, p = idx & (NPTS - 1);
        const float* xb = x + (size_t)b * 3 * NPTS;
        float px = xb[p], py = xb[NPTS + p], pz = xb[2 * NPTS + p];
        g_xp[idx] = make_float4(px, py, pz, -0.5f * (px*px + py*py + pz*pz));
    }
    if (blockIdx.x == 0 && threadIdx.x < CO) {
        int o = threadIdx.x;
        float inv   = gamma_[o] * rsqrtf(var_[o] + 1e-5f);
        float shift = beta_[o] - mean_[o] * inv;
        g_wf[2*o]   = make_float4(W[6*o+0], W[6*o+1], W[6*o+2], W[6*o+3]);
        g_wf[2*o+1] = make_float4(W[6*o+4], W[6*o+5], inv, shift);
    }
}

__global__ __launch_bounds__(CTA)
void edgeconv_kernel(float* __restrict__ out)
{
    __shared__ unsigned keysu[NPTS];       // 16 KB
    __shared__ int      hist[256];
    __shared__ int      warpTot[8], warpOff[8];
    __shared__ int      knn_s[KNN];
    __shared__ float4   nbr[KNN];
    __shared__ int      tie_idx[TIE_CAP];
    __shared__ unsigned tie_key[TIE_CAP];
    __shared__ int      s_cntW, s_cntT, s_need, s_cnt, s_shift, s_pb;
    __shared__ unsigned s_prefix;

    const int b    = blockIdx.y;
    const int n    = blockIdx.x;
    const int tid  = threadIdx.x;
    const int lane = tid & 31;
    const int wid  = tid >> 5;
    unsigned lt_mask; asm("mov.u32 %0, %%lanemask_lt;" : "=r"(lt_mask));

    const float4* __restrict__ xp = g_xp + (size_t)b * NPTS;
    const float4 q = xp[n];

    hist[tid] = 0;
    if (tid == 0) { s_cntW = 0; s_cntT = 0; s_need = KNN; s_cnt = 0; s_shift = 24; }
    __syncthreads();

    // ---- phase 1a: first 512 keys -> smem + full match-aggregated hist insert
    #pragma unroll
    for (int i = 0; i < PREI; i++) {
        int p = i * CTA + tid;
        float4 v = xp[p];
        float s = q.w + v.w;
        s = fmaf(q.x, v.x, fmaf(q.y, v.y, fmaf(q.z, v.z, s)));
        unsigned bb = __float_as_uint(s);
        unsigned u  = bb ^ (unsigned)(((int)bb >> 31) | 0x80000000);
        keysu[p] = u;
        int bin = (int)(u >> 24);
        unsigned mk = __match_any_sync(0xffffffffu, bin);
        if (!(mk & lt_mask)) atomicAdd(&hist[bin], __popc(mk));
    }
    __syncthreads();

    // ---- provisional threshold pb: >=KNN keys already at/above this bin,
    //      so the final threshold bin is provably >= pb.
    {
        int binv = hist[255 - tid];
        int cum = binv;
        #pragma unroll
        for (int off = 1; off < 32; off <<= 1) {
            int t = __shfl_up_sync(0xffffffffu, cum, off);
            if (lane >= off) cum += t;
        }
        if (lane == 31) warpTot[wid] = cum;
        __syncthreads();
        if (wid == 0) {
            int v = (lane < 8) ? warpTot[lane] : 0;
            int cc = v;
            #pragma unroll
            for (int off = 1; off < 8; off <<= 1) {
                int t = __shfl_up_sync(0xffffffffu, cc, off);
                if (lane >= off) cc += t;
            }
            if (lane < 8) warpOff[lane] = cc - v;
        }
        __syncthreads();
        int cumAll    = cum + warpOff[wid];
        int cumBefore = cumAll - binv;
        if (cumBefore < KNN && KNN <= cumAll) s_pb = 255 - tid;
        __syncthreads();
    }
    const int pb = s_pb;

    // ---- phase 1b: remaining keys -> smem; hist insert ONLY for bins >= pb
    //      (direct atomicAdd: survivors are sparse, conflicts rare)
    #pragma unroll
    for (int i = PREI; i < SLOTS; i++) {
        int p = i * CTA + tid;
        float4 v = xp[p];
        float s = q.w + v.w;
        s = fmaf(q.x, v.x, fmaf(q.y, v.y, fmaf(q.z, v.z, s)));
        unsigned bb = __float_as_uint(s);
        unsigned u  = bb ^ (unsigned)(((int)bb >> 31) | 0x80000000);
        keysu[p] = u;
        int bin = (int)(u >> 24);
        if (bin >= pb) atomicAdd(&hist[bin], 1);
    }
    __syncthreads();

    // ---- block-wide descending suffix scan over 256 bins (1 bin per thread)
    //      counts for bins >= pb are exact; threshold bin is always >= pb.
    {
        int binv = hist[255 - tid];
        int cum = binv;
        #pragma unroll
        for (int off = 1; off < 32; off <<= 1) {
            int t = __shfl_up_sync(0xffffffffu, cum, off);
            if (lane >= off) cum += t;
        }
        if (lane == 31) warpTot[wid] = cum;
        __syncthreads();
        if (wid == 0) {
            int v = (lane < 8) ? warpTot[lane] : 0;
            int cc = v;
            #pragma unroll
            for (int off = 1; off < 8; off <<= 1) {
                int t = __shfl_up_sync(0xffffffffu, cc, off);
                if (lane >= off) cc += t;
            }
            if (lane < 8) warpOff[lane] = cc - v;
        }
        __syncthreads();
        int cumAll    = cum + warpOff[wid];
        int cumBefore = cumAll - binv;
        if (cumBefore < KNN && KNN <= cumAll) {
            s_prefix = (unsigned)(255 - tid);
            s_need   = KNN - cumBefore;
            s_cnt    = binv;
        }
    }
    __syncthreads();

    // ---- fallback: refine threshold bin by 8 bits at a time (snapshot-disciplined)
    while (s_cnt > TIE_CAP && s_shift > 0) {
        const unsigned pf    = s_prefix;
        const int      sh    = s_shift;
        const int      nsh   = sh - 8;
        const int      needv = s_need;
        __syncthreads();
        hist[tid] = 0;
        __syncthreads();
        #pragma unroll
        for (int i = 0; i < SLOTS; i++) {
            unsigned u = keysu[i * CTA + tid];
            bool valid = (u >> sh) == pf;
            int bin = valid ? (int)((u >> nsh) & 255u) : -1;
            unsigned mk = __match_any_sync(0xffffffffu, bin);
            if (valid && !(mk & lt_mask)) atomicAdd(&hist[bin], __popc(mk));
        }
        __syncthreads();
        {
            int binv = hist[255 - tid];
            int cum = binv;
            #pragma unroll
            for (int off = 1; off < 32; off <<= 1) {
                int t = __shfl_up_sync(0xffffffffu, cum, off);
                if (lane >= off) cum += t;
            }
            if (lane == 31) warpTot[wid] = cum;
            __syncthreads();
            if (wid == 0) {
                int v = (lane < 8) ? warpTot[lane] : 0;
                int cc = v;
                #pragma unroll
                for (int off = 1; off < 8; off <<= 1) {
                    int t = __shfl_up_sync(0xffffffffu, cc, off);
                    if (lane >= off) cc += t;
                }
                if (lane < 8) warpOff[lane] = cc - v;
            }
            __syncthreads();
            int cumAll    = cum + warpOff[wid];
            int cumBefore = cumAll - binv;
            if (cumBefore < needv && needv <= cumAll) {
                s_prefix = (pf << 8) | (unsigned)(255 - tid);
                s_need   = needv - cumBefore;
                s_cnt    = binv;
                s_shift  = nsh;
            }
        }
        __syncthreads();
    }

    // ---- collect winners (unordered set) + boundary-bin tie candidates
    {
        const int      sh = s_shift;
        const unsigned pf = s_prefix;
        #pragma unroll
        for (int i = 0; i < SLOTS; i++) {
            int p = i * CTA + tid;
            unsigned u  = keysu[p];
            unsigned hi = u >> sh;
            if (hi >= pf) {
                if (hi > pf) {
                    knn_s[atomicAdd(&s_cntW, 1)] = p;
                } else {
                    int pos = atomicAdd(&s_cntT, 1);
                    if (pos < TIE_CAP) { tie_idx[pos] = p; tie_key[pos] = u; }
                }
            }
        }
    }
    __syncthreads();

    // ---- parallel exact tie resolve: rank by (value desc, index asc)
    {
        int cnt   = s_cntT < TIE_CAP ? s_cntT : TIE_CAP;
        int needf = s_need;
        int baseW = s_cntW;
        if (tid < cnt) {
            unsigned mk = tie_key[tid]; int mi = tie_idx[tid];
            int rank = 0;
            for (int j = 0; j < cnt; j++) {
                unsigned kj = tie_key[j]; int ij = tie_idx[j];
                rank += (kj > mk) || (kj == mk && ij < mi);
            }
            if (rank < needf) knn_s[baseW + rank] = mi;
        }
    }
    __syncthreads();

    // ---- gather neighbor coords
    if (tid < KNN) nbr[tid] = xp[knn_s[tid]];
    __syncthreads();

    // ---- edge MLP: 4 threads per output channel, 5 k's each, shfl-combine
    {
        const int o = tid >> 2;
        const int c = tid & 3;
        const float4 wa = g_wf[2*o];      // w0 w1 w2 w3
        const float4 wb = g_wf[2*o + 1];  // w4 w5 inv shift
        const float cpart = fmaf(q.x, wa.w, fmaf(q.y, wb.x, q.z * wb.y));

        float m = -3.4028235e38f;
        #pragma unroll
        for (int k = 0; k < 5; k++) {
            float4 p = nbr[c * 5 + k];
            float y = fmaf(p.x - q.x, wa.x,
                      fmaf(p.y - q.y, wa.y,
                      fmaf(p.z - q.z, wa.z, cpart)));
            y = fmaf(y, wb.z, wb.w);
            y = (y >= 0.0f) ? y : 0.2f * y;
            m = fmaxf(m, y);
        }
        m = fmaxf(m, __shfl_xor_sync(0xffffffffu, m, 1));
        m = fmaxf(m, __shfl_xor_sync(0xffffffffu, m, 2));
        if (c == 0)
            out[(size_t)b * CO * NPTS + (size_t)o * NPTS + n] = m;
    }
}

extern "C" void kernel_launch(void* const* d_in, const int* in_sizes, int n_in,
                              void* d_out, int out_size)
{
    const float* x      = (const float*)d_in[0];
    const float* W      = (const float*)d_in[1];
    const float* gamma_ = (const float*)d_in[2];
    const float* beta_  = (const float*)d_in[3];
    const float* mean_  = (const float*)d_in[4];
    const float* var_   = (const float*)d_in[5];
    float* out = (float*)d_out;

    prep_kernel<<<(NB * NPTS + 255) / 256, 256>>>(x, W, gamma_, beta_, mean_, var_);
    dim3 grid(NPTS, NB);
    edgeconv_kernel<<<grid, CTA>>>(out);
}